// round 1
// baseline (speedup 1.0000x reference)
#include <cuda_runtime.h>

#define NN 100000
#define EE 3200000

typedef unsigned long long u64;

// ---------------- scratch (device globals; no dynamic allocation) ----------------
__device__ __align__(16) float g_h[NN * 16];     // h = x @ W1
__device__ __align__(16) float g_num[NN * 16];   // layer1 numerator accumulator
__device__ __align__(16) float g_psrc[NN * 16];  // h1 @ mw0[0:16]
__device__ __align__(16) float g_pdst[NN * 16];  // h1 @ mw0[19:35]
__device__ __align__(16) float g_h2[NN * 2];     // h1 @ W2
__device__ __align__(16) float g_num2[NN * 2];   // layer2 numerator accumulator
__device__ float g_als[NN], g_ald[NN];           // layer1 attention halves
__device__ float g_denom[NN];
__device__ float g_al2s[NN], g_al2d[NN];         // layer2 attention halves
__device__ float g_denom2[NN];
__device__ float g_easum[3];                     // sum of edge_attr (for self-loop mean)
__device__ float g_esum[4];                      // sum of e (for layer2 self-loop mean)
__device__ float g_c1[3];                        // We1 @ ae1
__device__ float g_c2[4];                        // We2 @ ae2

// ---------------- helpers ----------------
__device__ __forceinline__ float leaky(float x) { return x > 0.f ? x : 0.2f * x; }

__device__ __forceinline__ u64 pack2(float x) {
    u64 r; asm("mov.b64 %0, {%1, %1};" : "=l"(r) : "f"(x)); return r;
}
__device__ __forceinline__ u64 fma2(u64 a, u64 b, u64 c) {
    u64 d; asm("fma.rn.f32x2 %0, %1, %2, %3;" : "=l"(d) : "l"(a), "l"(b), "l"(c)); return d;
}
__device__ __forceinline__ u64 add2(u64 a, u64 b) {
    u64 d; asm("add.rn.f32x2 %0, %1, %2;" : "=l"(d) : "l"(a), "l"(b)); return d;
}
__device__ __forceinline__ void unpack2(u64 a, float& x, float& y) {
    asm("mov.b64 {%0, %1}, %2;" : "=f"(x), "=f"(y) : "l"(a));
}

// ---------------- K0: constants + tiny zeroing ----------------
__global__ void k_prep(const float* __restrict__ We1, const float* __restrict__ ae1,
                       const float* __restrict__ We2, const float* __restrict__ ae2) {
    int t = threadIdx.x;
    if (t < 3) {
        float s = 0.f;
        #pragma unroll
        for (int k = 0; k < 16; k++) s += We1[t * 16 + k] * ae1[k];
        g_c1[t] = s;
        g_easum[t] = 0.f;
    }
    if (t < 4) {
        float s = 0.f;
        #pragma unroll
        for (int k = 0; k < 2; k++) s += We2[t * 2 + k] * ae2[k];
        g_c2[t] = s;
        g_esum[t] = 0.f;
    }
}

// ---------------- K1: per-node layer-1 precompute + zero accumulators ----------------
__global__ void __launch_bounds__(256) k_node1(const float* __restrict__ x,
                                               const float* __restrict__ W1,
                                               const float* __restrict__ as1,
                                               const float* __restrict__ ad1) {
    __shared__ float sW[64], sa[16], sd[16];
    int t = threadIdx.x;
    if (t < 64) sW[t] = W1[t];
    if (t >= 64 && t < 80) sa[t - 64] = as1[t - 64];
    if (t >= 80 && t < 96) sd[t - 80] = ad1[t - 80];
    __syncthreads();
    int n = blockIdx.x * 256 + t;
    if (n >= NN) return;
    const float4 xv = reinterpret_cast<const float4*>(x)[n];
    float als = 0.f, ald = 0.f;
    #pragma unroll
    for (int j = 0; j < 16; j++) {
        float h = xv.x * sW[j] + xv.y * sW[16 + j] + xv.z * sW[32 + j] + xv.w * sW[48 + j];
        g_h[n * 16 + j] = h;
        g_num[n * 16 + j] = 0.f;
        als += h * sa[j];
        ald += h * sd[j];
    }
    g_als[n] = als;
    g_ald[n] = ald;
    g_denom[n] = 0.f;
    g_denom2[n] = 0.f;
    g_num2[n * 2] = 0.f;
    g_num2[n * 2 + 1] = 0.f;
}

// ---------------- K2: mean(edge_attr) reduction ----------------
__global__ void __launch_bounds__(256) k_eamean(const float* __restrict__ ea) {
    float s0 = 0.f, s1 = 0.f, s2 = 0.f;
    for (int e = blockIdx.x * 256 + threadIdx.x; e < EE; e += gridDim.x * 256) {
        s0 += ea[e * 3 + 0];
        s1 += ea[e * 3 + 1];
        s2 += ea[e * 3 + 2];
    }
    #pragma unroll
    for (int o = 16; o > 0; o >>= 1) {
        s0 += __shfl_down_sync(0xffffffffu, s0, o);
        s1 += __shfl_down_sync(0xffffffffu, s1, o);
        s2 += __shfl_down_sync(0xffffffffu, s2, o);
    }
    __shared__ float sh[24];
    int w = threadIdx.x >> 5;
    if ((threadIdx.x & 31) == 0) { sh[w] = s0; sh[8 + w] = s1; sh[16 + w] = s2; }
    __syncthreads();
    if (threadIdx.x == 0) {
        float a = 0.f, b = 0.f, c = 0.f;
        #pragma unroll
        for (int i = 0; i < 8; i++) { a += sh[i]; b += sh[8 + i]; c += sh[16 + i]; }
        atomicAdd(&g_easum[0], a);
        atomicAdd(&g_easum[1], b);
        atomicAdd(&g_easum[2], c);
    }
}

// ---------------- K3: layer-1 edge pass (softmax-weighted scatter) ----------------
__global__ void __launch_bounds__(256) k_edge1(const int* __restrict__ src,
                                               const int* __restrict__ dst,
                                               const float* __restrict__ ea) {
    int e = blockIdx.x * 256 + threadIdx.x;  // grid covers EE exactly
    int s = src[e], d = dst[e];
    float c0 = g_c1[0], c1 = g_c1[1], c2 = g_c1[2];
    float a = g_als[s] + g_ald[d] + ea[e * 3] * c0 + ea[e * 3 + 1] * c1 + ea[e * 3 + 2] * c2;
    float ex = __expf(leaky(a));
    atomicAdd(&g_denom[d], ex);
    const float4* hs = reinterpret_cast<const float4*>(g_h + (size_t)s * 16);
    float* nd = g_num + (size_t)d * 16;
    #pragma unroll
    for (int q = 0; q < 4; q++) {
        float4 hv = hs[q];
        atomicAdd(nd + q * 4 + 0, ex * hv.x);
        atomicAdd(nd + q * 4 + 1, ex * hv.y);
        atomicAdd(nd + q * 4 + 2, ex * hv.z);
        atomicAdd(nd + q * 4 + 3, ex * hv.w);
    }
}

// ---------------- K4: finalize layer 1 + derive per-node layer-2 quantities ----------------
__global__ void __launch_bounds__(256) k_node2(const float* __restrict__ b1,
                                               const float* __restrict__ mw0,
                                               const float* __restrict__ W2,
                                               const float* __restrict__ as2,
                                               const float* __restrict__ ad2) {
    __shared__ float sws[256];  // mw0 rows 0..15
    __shared__ float swd[256];  // mw0 rows 19..34
    __shared__ float sb1[16], sW2[32], sas2[2], sad2[2];
    int t = threadIdx.x;
    sws[t] = mw0[t];
    swd[t] = mw0[19 * 16 + t];
    if (t < 16) sb1[t] = b1[t];
    if (t >= 16 && t < 48) sW2[t - 16] = W2[t - 16];
    if (t >= 48 && t < 50) sas2[t - 48] = as2[t - 48];
    if (t >= 50 && t < 52) sad2[t - 50] = ad2[t - 50];
    __syncthreads();
    int n = blockIdx.x * 256 + t;
    if (n >= NN) return;

    const float invE = 1.f / (float)EE;
    float m0 = g_easum[0] * invE, m1 = g_easum[1] * invE, m2 = g_easum[2] * invE;
    float aself = leaky(g_als[n] + g_ald[n] + m0 * g_c1[0] + m1 * g_c1[1] + m2 * g_c1[2]);
    float ex = __expf(aself);
    float inv = 1.f / (g_denom[n] + ex + 1e-16f);

    float h1[16];
    #pragma unroll
    for (int j = 0; j < 16; j++)
        h1[j] = (g_num[n * 16 + j] + ex * g_h[n * 16 + j]) * inv + sb1[j];

    #pragma unroll
    for (int j = 0; j < 16; j++) {
        float ps = 0.f, pd = 0.f;
        #pragma unroll
        for (int i = 0; i < 16; i++) {
            ps += h1[i] * sws[i * 16 + j];
            pd += h1[i] * swd[i * 16 + j];
        }
        g_psrc[n * 16 + j] = ps;
        g_pdst[n * 16 + j] = pd;
    }
    float h20 = 0.f, h21 = 0.f;
    #pragma unroll
    for (int i = 0; i < 16; i++) {
        h20 += h1[i] * sW2[i * 2];
        h21 += h1[i] * sW2[i * 2 + 1];
    }
    g_h2[n * 2] = h20;
    g_h2[n * 2 + 1] = h21;
    g_al2s[n] = h20 * sas2[0] + h21 * sas2[1];
    g_al2d[n] = h20 * sad2[0] + h21 * sad2[1];
}

// ---------------- K5: edge MLP (f32x2 packed) + layer-2 edge pass + log_softmax(e) ----------------
__global__ void __launch_bounds__(256) k_edge2(const int* __restrict__ src,
                                               const int* __restrict__ dst,
                                               const float* __restrict__ ea,
                                               const float* __restrict__ mw0,
                                               const float* __restrict__ mb0,
                                               const float* __restrict__ mw1,
                                               const float* __restrict__ mb1,
                                               const float* __restrict__ mw2,
                                               const float* __restrict__ mb2,
                                               const float* __restrict__ mw3,
                                               const float* __restrict__ mb3,
                                               float* __restrict__ out_e) {
    // weights stored as packed f32 pairs
    __shared__ u64 s_w0[24];      // mw0 rows 16..18  (3 x 8 pairs)
    __shared__ u64 s_b0[8];
    __shared__ u64 s_w1[128];     // 16 x 8 pairs
    __shared__ u64 s_b1[8];
    __shared__ u64 s_w2[64];      // 16 x 4 pairs
    __shared__ u64 s_b2[4];
    __shared__ u64 s_w3[16];      // 8 x 2 pairs
    __shared__ u64 s_b3[2];
    __shared__ float s_c2[4];
    __shared__ float sred[32];

    int t = threadIdx.x;
    {
        const u64* w0g = reinterpret_cast<const u64*>(mw0);
        if (t < 24) s_w0[t] = w0g[128 + t];
        if (t >= 32 && t < 160) s_w1[t - 32] = reinterpret_cast<const u64*>(mw1)[t - 32];
        if (t >= 160 && t < 224) s_w2[t - 160] = reinterpret_cast<const u64*>(mw2)[t - 160];
        if (t >= 224 && t < 240) s_w3[t - 224] = reinterpret_cast<const u64*>(mw3)[t - 224];
        if (t >= 240 && t < 248) s_b0[t - 240] = reinterpret_cast<const u64*>(mb0)[t - 240];
        if (t >= 248 && t < 256) s_b1[t - 248] = reinterpret_cast<const u64*>(mb1)[t - 248];
        if (t >= 24 && t < 28) s_b2[t - 24] = reinterpret_cast<const u64*>(mb2)[t - 24];
        if (t >= 28 && t < 30) s_b3[t - 28] = reinterpret_cast<const u64*>(mb3)[t - 28];
        if (t >= 30 && t < 32) { }  // spare
        if (t < 4) s_c2[t] = g_c2[t];
    }
    __syncthreads();

    int e = blockIdx.x * 256 + t;  // EE = 12500*256 exactly
    int s = src[e], d = dst[e];
    float ea0 = ea[e * 3], ea1 = ea[e * 3 + 1], ea2 = ea[e * 3 + 2];

    // layer 0: psrc[s] + pdst[d] + ea @ w0e + b0, relu
    const u64* ps = reinterpret_cast<const u64*>(g_psrc) + (size_t)s * 8;
    const u64* pd = reinterpret_cast<const u64*>(g_pdst) + (size_t)d * 8;
    u64 v0 = pack2(ea0), v1 = pack2(ea1), v2 = pack2(ea2);
    float t0[16];
    #pragma unroll
    for (int p = 0; p < 8; p++) {
        u64 a = add2(ps[p], pd[p]);
        a = add2(a, s_b0[p]);
        a = fma2(v0, s_w0[p], a);
        a = fma2(v1, s_w0[8 + p], a);
        a = fma2(v2, s_w0[16 + p], a);
        float lo, hi;
        unpack2(a, lo, hi);
        t0[2 * p] = fmaxf(lo, 0.f);
        t0[2 * p + 1] = fmaxf(hi, 0.f);
    }

    // layer 1: 16 -> 16, relu
    u64 acc1[8];
    #pragma unroll
    for (int p = 0; p < 8; p++) acc1[p] = s_b1[p];
    #pragma unroll
    for (int i = 0; i < 16; i++) {
        u64 bi = pack2(t0[i]);
        #pragma unroll
        for (int p = 0; p < 8; p++) acc1[p] = fma2(bi, s_w1[i * 8 + p], acc1[p]);
    }
    float t1[16];
    #pragma unroll
    for (int p = 0; p < 8; p++) {
        float lo, hi;
        unpack2(acc1[p], lo, hi);
        t1[2 * p] = fmaxf(lo, 0.f);
        t1[2 * p + 1] = fmaxf(hi, 0.f);
    }

    // layer 2: 16 -> 8, relu
    u64 acc2[4];
    #pragma unroll
    for (int p = 0; p < 4; p++) acc2[p] = s_b2[p];
    #pragma unroll
    for (int i = 0; i < 16; i++) {
        u64 bi = pack2(t1[i]);
        #pragma unroll
        for (int p = 0; p < 4; p++) acc2[p] = fma2(bi, s_w2[i * 4 + p], acc2[p]);
    }
    float t2[8];
    #pragma unroll
    for (int p = 0; p < 4; p++) {
        float lo, hi;
        unpack2(acc2[p], lo, hi);
        t2[2 * p] = fmaxf(lo, 0.f);
        t2[2 * p + 1] = fmaxf(hi, 0.f);
    }

    // layer 3: 8 -> 4
    u64 acc3[2];
    acc3[0] = s_b3[0];
    acc3[1] = s_b3[1];
    #pragma unroll
    for (int i = 0; i < 8; i++) {
        u64 bi = pack2(t2[i]);
        acc3[0] = fma2(bi, s_w3[i * 2], acc3[0]);
        acc3[1] = fma2(bi, s_w3[i * 2 + 1], acc3[1]);
    }
    float e0, e1, e2, e3;
    unpack2(acc3[0], e0, e1);
    unpack2(acc3[1], e2, e3);

    // log_softmax(e) -> output region 2
    float mx = fmaxf(fmaxf(e0, e1), fmaxf(e2, e3));
    float x0 = __expf(e0 - mx), x1 = __expf(e1 - mx), x2 = __expf(e2 - mx), x3 = __expf(e3 - mx);
    float lse = mx + __logf(x0 + x1 + x2 + x3);
    reinterpret_cast<float4*>(out_e)[e] = make_float4(e0 - lse, e1 - lse, e2 - lse, e3 - lse);

    // layer-2 attention scatter
    float alpha = g_al2s[s] + g_al2d[d] + e0 * s_c2[0] + e1 * s_c2[1] + e2 * s_c2[2] + e3 * s_c2[3];
    float ex2 = __expf(leaky(alpha));
    atomicAdd(&g_denom2[d], ex2);
    float h20 = g_h2[s * 2], h21 = g_h2[s * 2 + 1];
    atomicAdd(&g_num2[(size_t)d * 2], ex2 * h20);
    atomicAdd(&g_num2[(size_t)d * 2 + 1], ex2 * h21);

    // block-reduce sum of e for layer-2 self-loop mean
    float r0 = e0, r1 = e1, r2 = e2, r3 = e3;
    #pragma unroll
    for (int o = 16; o > 0; o >>= 1) {
        r0 += __shfl_down_sync(0xffffffffu, r0, o);
        r1 += __shfl_down_sync(0xffffffffu, r1, o);
        r2 += __shfl_down_sync(0xffffffffu, r2, o);
        r3 += __shfl_down_sync(0xffffffffu, r3, o);
    }
    int w = t >> 5;
    if ((t & 31) == 0) { sred[w * 4] = r0; sred[w * 4 + 1] = r1; sred[w * 4 + 2] = r2; sred[w * 4 + 3] = r3; }
    __syncthreads();
    if (t < 4) {
        float sAcc = 0.f;
        #pragma unroll
        for (int i = 0; i < 8; i++) sAcc += sred[i * 4 + t];
        atomicAdd(&g_esum[t], sAcc);
    }
}

// ---------------- K6: finalize layer 2 + node log_softmax ----------------
__global__ void __launch_bounds__(256) k_node3(const float* __restrict__ b2,
                                               float* __restrict__ out_n) {
    int n = blockIdx.x * 256 + threadIdx.x;
    if (n >= NN) return;
    const float invE = 1.f / (float)EE;
    float a = g_al2s[n] + g_al2d[n];
    #pragma unroll
    for (int j = 0; j < 4; j++) a += g_esum[j] * invE * g_c2[j];
    float ex = __expf(leaky(a));
    float den = 1.f / (g_denom2[n] + ex + 1e-16f);
    float o0 = (g_num2[n * 2] + ex * g_h2[n * 2]) * den + b2[0];
    float o1 = (g_num2[n * 2 + 1] + ex * g_h2[n * 2 + 1]) * den + b2[1];
    float m = fmaxf(o0, o1);
    float l = m + __logf(__expf(o0 - m) + __expf(o1 - m));
    reinterpret_cast<float2*>(out_n)[n] = make_float2(o0 - l, o1 - l);
}

// ---------------- launch ----------------
extern "C" void kernel_launch(void* const* d_in, const int* in_sizes, int n_in,
                              void* d_out, int out_size) {
    const float* x   = (const float*)d_in[0];
    const float* ea  = (const float*)d_in[1];
    const float* W1  = (const float*)d_in[2];
    const float* as1 = (const float*)d_in[3];
    const float* ad1 = (const float*)d_in[4];
    const float* We1 = (const float*)d_in[5];
    const float* ae1 = (const float*)d_in[6];
    const float* b1  = (const float*)d_in[7];
    const float* mw0 = (const float*)d_in[8];
    const float* mb0 = (const float*)d_in[9];
    const float* mw1 = (const float*)d_in[10];
    const float* mb1 = (const float*)d_in[11];
    const float* mw2 = (const float*)d_in[12];
    const float* mb2 = (const float*)d_in[13];
    const float* mw3 = (const float*)d_in[14];
    const float* mb3 = (const float*)d_in[15];
    const float* W2  = (const float*)d_in[16];
    const float* as2 = (const float*)d_in[17];
    const float* ad2 = (const float*)d_in[18];
    const float* We2 = (const float*)d_in[19];
    const float* ae2 = (const float*)d_in[20];
    const float* b2  = (const float*)d_in[21];
    const int* ei    = (const int*)d_in[22];
    const int* srcp = ei;
    const int* dstp = ei + EE;
    float* out = (float*)d_out;

    k_prep<<<1, 32>>>(We1, ae1, We2, ae2);
    k_node1<<<(NN + 255) / 256, 256>>>(x, W1, as1, ad1);
    k_eamean<<<592, 256>>>(ea);
    k_edge1<<<EE / 256, 256>>>(srcp, dstp, ea);
    k_node2<<<(NN + 255) / 256, 256>>>(b1, mw0, W2, as2, ad2);
    k_edge2<<<EE / 256, 256>>>(srcp, dstp, ea, mw0, mb0, mw1, mb1, mw2, mb2, mw3, mb3,
                               out + 2 * NN);
    k_node3<<<(NN + 255) / 256, 256>>>(b2, out);
}

// round 2
// speedup vs baseline: 1.7758x; 1.7758x over previous
#include <cuda_runtime.h>

#define NN 100000
#define EE 3200000

typedef unsigned long long u64;

// ---------------- scratch (device globals; no dynamic allocation) ----------------
__device__ __align__(16) float g_acc1[NN * 4];   // layer1: sum ex * x[s]  (4-dim!)
__device__ __align__(16) float g_acc2[NN * 4];   // layer2: {sum ex*h20, sum ex*h21, sum ex, pad}
__device__ __align__(16) float g_psrc[NN * 16];  // h1 @ mw0[0:16]
__device__ __align__(16) float g_pdst[NN * 16];  // h1 @ mw0[19:35]
__device__ __align__(16) float g_h2[NN * 2];     // h1 @ W2
__device__ float g_als[NN], g_ald[NN];           // layer1 attention halves
__device__ float g_denom[NN];
__device__ float g_al2s[NN], g_al2d[NN];         // layer2 attention halves
__device__ float g_easum[3];                     // sum of edge_attr (for self-loop mean)
__device__ float g_esum[4];                      // sum of e (for layer2 self-loop mean)
__device__ float g_c1[3];                        // We1 @ ae1
__device__ float g_c2[4];                        // We2 @ ae2

// ---------------- helpers ----------------
__device__ __forceinline__ float leaky(float x) { return x > 0.f ? x : 0.2f * x; }

__device__ __forceinline__ u64 pack2(float x) {
    u64 r; asm("mov.b64 %0, {%1, %1};" : "=l"(r) : "f"(x)); return r;
}
__device__ __forceinline__ u64 fma2(u64 a, u64 b, u64 c) {
    u64 d; asm("fma.rn.f32x2 %0, %1, %2, %3;" : "=l"(d) : "l"(a), "l"(b), "l"(c)); return d;
}
__device__ __forceinline__ u64 add2(u64 a, u64 b) {
    u64 d; asm("add.rn.f32x2 %0, %1, %2;" : "=l"(d) : "l"(a), "l"(b)); return d;
}
__device__ __forceinline__ void unpack2(u64 a, float& x, float& y) {
    asm("mov.b64 {%0, %1}, %2;" : "=f"(x), "=f"(y) : "l"(a));
}
__device__ __forceinline__ void red_v4(float* p, float a, float b, float c, float d) {
    asm volatile("red.global.add.v4.f32 [%0], {%1, %2, %3, %4};"
                 :: "l"(p), "f"(a), "f"(b), "f"(c), "f"(d) : "memory");
}
__device__ __forceinline__ void red_f32(float* p, float v) {
    asm volatile("red.global.add.f32 [%0], %1;" :: "l"(p), "f"(v) : "memory");
}

// ---------------- K0: constants + tiny zeroing ----------------
__global__ void k_prep(const float* __restrict__ We1, const float* __restrict__ ae1,
                       const float* __restrict__ We2, const float* __restrict__ ae2) {
    int t = threadIdx.x;
    if (t < 3) {
        float s = 0.f;
        #pragma unroll
        for (int k = 0; k < 16; k++) s += We1[t * 16 + k] * ae1[k];
        g_c1[t] = s;
        g_easum[t] = 0.f;
    }
    if (t < 4) {
        float s = 0.f;
        #pragma unroll
        for (int k = 0; k < 2; k++) s += We2[t * 2 + k] * ae2[k];
        g_c2[t] = s;
        g_esum[t] = 0.f;
    }
}

// ---------------- K1: per-node layer-1 precompute + zero accumulators ----------------
__global__ void __launch_bounds__(256) k_node1(const float* __restrict__ x,
                                               const float* __restrict__ W1,
                                               const float* __restrict__ as1,
                                               const float* __restrict__ ad1) {
    __shared__ float sW[64], sa[16], sd[16];
    int t = threadIdx.x;
    if (t < 64) sW[t] = W1[t];
    if (t >= 64 && t < 80) sa[t - 64] = as1[t - 64];
    if (t >= 80 && t < 96) sd[t - 80] = ad1[t - 80];
    __syncthreads();
    int n = blockIdx.x * 256 + t;
    if (n >= NN) return;
    const float4 xv = reinterpret_cast<const float4*>(x)[n];
    float als = 0.f, ald = 0.f;
    #pragma unroll
    for (int j = 0; j < 16; j++) {
        float h = xv.x * sW[j] + xv.y * sW[16 + j] + xv.z * sW[32 + j] + xv.w * sW[48 + j];
        als += h * sa[j];
        ald += h * sd[j];
    }
    g_als[n] = als;
    g_ald[n] = ald;
    g_denom[n] = 0.f;
    reinterpret_cast<float4*>(g_acc1)[n] = make_float4(0.f, 0.f, 0.f, 0.f);
    reinterpret_cast<float4*>(g_acc2)[n] = make_float4(0.f, 0.f, 0.f, 0.f);
}

// ---------------- K2: mean(edge_attr) reduction ----------------
__global__ void __launch_bounds__(256) k_eamean(const float* __restrict__ ea) {
    float s0 = 0.f, s1 = 0.f, s2 = 0.f;
    for (int e = blockIdx.x * 256 + threadIdx.x; e < EE; e += gridDim.x * 256) {
        s0 += ea[e * 3 + 0];
        s1 += ea[e * 3 + 1];
        s2 += ea[e * 3 + 2];
    }
    #pragma unroll
    for (int o = 16; o > 0; o >>= 1) {
        s0 += __shfl_down_sync(0xffffffffu, s0, o);
        s1 += __shfl_down_sync(0xffffffffu, s1, o);
        s2 += __shfl_down_sync(0xffffffffu, s2, o);
    }
    __shared__ float sh[24];
    int w = threadIdx.x >> 5;
    if ((threadIdx.x & 31) == 0) { sh[w] = s0; sh[8 + w] = s1; sh[16 + w] = s2; }
    __syncthreads();
    if (threadIdx.x == 0) {
        float a = 0.f, b = 0.f, c = 0.f;
        #pragma unroll
        for (int i = 0; i < 8; i++) { a += sh[i]; b += sh[8 + i]; c += sh[16 + i]; }
        atomicAdd(&g_easum[0], a);
        atomicAdd(&g_easum[1], b);
        atomicAdd(&g_easum[2], c);
    }
}

// ---------------- K3: layer-1 edge pass (scatter ex*x[s], 4-dim payload) ----------------
__global__ void __launch_bounds__(256) k_edge1(const int* __restrict__ src,
                                               const int* __restrict__ dst,
                                               const float* __restrict__ ea,
                                               const float* __restrict__ x) {
    int e = blockIdx.x * 256 + threadIdx.x;  // grid covers EE exactly
    int s = src[e], d = dst[e];
    float c0 = g_c1[0], c1 = g_c1[1], c2 = g_c1[2];
    float a = g_als[s] + g_ald[d] + ea[e * 3] * c0 + ea[e * 3 + 1] * c1 + ea[e * 3 + 2] * c2;
    float ex = __expf(leaky(a));
    const float4 xv = reinterpret_cast<const float4*>(x)[s];
    red_v4(g_acc1 + (size_t)d * 4, ex * xv.x, ex * xv.y, ex * xv.z, ex * xv.w);
    red_f32(g_denom + d, ex);
}

// ---------------- K4: finalize layer 1 + derive per-node layer-2 quantities ----------------
__global__ void __launch_bounds__(256) k_node2(const float* __restrict__ x,
                                               const float* __restrict__ W1,
                                               const float* __restrict__ b1,
                                               const float* __restrict__ mw0,
                                               const float* __restrict__ W2,
                                               const float* __restrict__ as2,
                                               const float* __restrict__ ad2) {
    __shared__ float sws[256];  // mw0 rows 0..15
    __shared__ float swd[256];  // mw0 rows 19..34
    __shared__ float sW1[64], sb1[16], sW2[32], sas2[2], sad2[2];
    int t = threadIdx.x;
    sws[t] = mw0[t];
    swd[t] = mw0[19 * 16 + t];
    if (t < 64) sW1[t] = W1[t];
    if (t >= 64 && t < 80) sb1[t - 64] = b1[t - 64];
    if (t >= 80 && t < 112) sW2[t - 80] = W2[t - 80];
    if (t >= 112 && t < 114) sas2[t - 112] = as2[t - 112];
    if (t >= 114 && t < 116) sad2[t - 114] = ad2[t - 114];
    __syncthreads();
    int n = blockIdx.x * 256 + t;
    if (n >= NN) return;

    const float invE = 1.f / (float)EE;
    float m0 = g_easum[0] * invE, m1 = g_easum[1] * invE, m2 = g_easum[2] * invE;
    float aself = leaky(g_als[n] + g_ald[n] + m0 * g_c1[0] + m1 * g_c1[1] + m2 * g_c1[2]);
    float ex = __expf(aself);
    float inv = 1.f / (g_denom[n] + ex + 1e-16f);

    float4 acc = reinterpret_cast<const float4*>(g_acc1)[n];
    const float4 xv = reinterpret_cast<const float4*>(x)[n];
    acc.x += ex * xv.x;
    acc.y += ex * xv.y;
    acc.z += ex * xv.z;
    acc.w += ex * xv.w;

    float h1[16];
    #pragma unroll
    for (int j = 0; j < 16; j++) {
        float h = acc.x * sW1[j] + acc.y * sW1[16 + j] + acc.z * sW1[32 + j] + acc.w * sW1[48 + j];
        h1[j] = h * inv + sb1[j];
    }

    #pragma unroll
    for (int j = 0; j < 16; j++) {
        float ps = 0.f, pd = 0.f;
        #pragma unroll
        for (int i = 0; i < 16; i++) {
            ps += h1[i] * sws[i * 16 + j];
            pd += h1[i] * swd[i * 16 + j];
        }
        g_psrc[n * 16 + j] = ps;
        g_pdst[n * 16 + j] = pd;
    }
    float h20 = 0.f, h21 = 0.f;
    #pragma unroll
    for (int i = 0; i < 16; i++) {
        h20 += h1[i] * sW2[i * 2];
        h21 += h1[i] * sW2[i * 2 + 1];
    }
    g_h2[n * 2] = h20;
    g_h2[n * 2 + 1] = h21;
    g_al2s[n] = h20 * sas2[0] + h21 * sas2[1];
    g_al2d[n] = h20 * sad2[0] + h21 * sad2[1];
}

// ---------------- K5: edge MLP (f32x2 packed) + layer-2 edge pass + log_softmax(e) ----------------
__global__ void __launch_bounds__(256) k_edge2(const int* __restrict__ src,
                                               const int* __restrict__ dst,
                                               const float* __restrict__ ea,
                                               const float* __restrict__ mw0,
                                               const float* __restrict__ mb0,
                                               const float* __restrict__ mw1,
                                               const float* __restrict__ mb1,
                                               const float* __restrict__ mw2,
                                               const float* __restrict__ mb2,
                                               const float* __restrict__ mw3,
                                               const float* __restrict__ mb3,
                                               float* __restrict__ out_e) {
    // weights stored as packed f32 pairs
    __shared__ u64 s_w0[24];      // mw0 rows 16..18  (3 x 8 pairs)
    __shared__ u64 s_b0[8];
    __shared__ u64 s_w1[128];     // 16 x 8 pairs
    __shared__ u64 s_b1[8];
    __shared__ u64 s_w2[64];      // 16 x 4 pairs
    __shared__ u64 s_b2[4];
    __shared__ u64 s_w3[16];      // 8 x 2 pairs
    __shared__ u64 s_b3[2];
    __shared__ float s_c2[4];
    __shared__ float sred[32];

    int t = threadIdx.x;
    {
        const u64* w0g = reinterpret_cast<const u64*>(mw0);
        if (t < 24) s_w0[t] = w0g[128 + t];
        if (t >= 32 && t < 160) s_w1[t - 32] = reinterpret_cast<const u64*>(mw1)[t - 32];
        if (t >= 160 && t < 224) s_w2[t - 160] = reinterpret_cast<const u64*>(mw2)[t - 160];
        if (t >= 224 && t < 240) s_w3[t - 224] = reinterpret_cast<const u64*>(mw3)[t - 224];
        if (t >= 240 && t < 248) s_b0[t - 240] = reinterpret_cast<const u64*>(mb0)[t - 240];
        if (t >= 248 && t < 256) s_b1[t - 248] = reinterpret_cast<const u64*>(mb1)[t - 248];
        if (t >= 24 && t < 28) s_b2[t - 24] = reinterpret_cast<const u64*>(mb2)[t - 24];
        if (t >= 28 && t < 30) s_b3[t - 28] = reinterpret_cast<const u64*>(mb3)[t - 28];
        if (t < 4) s_c2[t] = g_c2[t];
    }
    __syncthreads();

    int e = blockIdx.x * 256 + t;  // EE = 12500*256 exactly
    int s = src[e], d = dst[e];
    float ea0 = ea[e * 3], ea1 = ea[e * 3 + 1], ea2 = ea[e * 3 + 2];

    // layer 0: psrc[s] + pdst[d] + ea @ w0e + b0, relu
    const u64* ps = reinterpret_cast<const u64*>(g_psrc) + (size_t)s * 8;
    const u64* pd = reinterpret_cast<const u64*>(g_pdst) + (size_t)d * 8;
    u64 v0 = pack2(ea0), v1 = pack2(ea1), v2 = pack2(ea2);
    float t0[16];
    #pragma unroll
    for (int p = 0; p < 8; p++) {
        u64 a = add2(ps[p], pd[p]);
        a = add2(a, s_b0[p]);
        a = fma2(v0, s_w0[p], a);
        a = fma2(v1, s_w0[8 + p], a);
        a = fma2(v2, s_w0[16 + p], a);
        float lo, hi;
        unpack2(a, lo, hi);
        t0[2 * p] = fmaxf(lo, 0.f);
        t0[2 * p + 1] = fmaxf(hi, 0.f);
    }

    // layer 1: 16 -> 16, relu
    u64 acc1[8];
    #pragma unroll
    for (int p = 0; p < 8; p++) acc1[p] = s_b1[p];
    #pragma unroll
    for (int i = 0; i < 16; i++) {
        u64 bi = pack2(t0[i]);
        #pragma unroll
        for (int p = 0; p < 8; p++) acc1[p] = fma2(bi, s_w1[i * 8 + p], acc1[p]);
    }
    float t1[16];
    #pragma unroll
    for (int p = 0; p < 8; p++) {
        float lo, hi;
        unpack2(acc1[p], lo, hi);
        t1[2 * p] = fmaxf(lo, 0.f);
        t1[2 * p + 1] = fmaxf(hi, 0.f);
    }

    // layer 2: 16 -> 8, relu
    u64 acc2[4];
    #pragma unroll
    for (int p = 0; p < 4; p++) acc2[p] = s_b2[p];
    #pragma unroll
    for (int i = 0; i < 16; i++) {
        u64 bi = pack2(t1[i]);
        #pragma unroll
        for (int p = 0; p < 4; p++) acc2[p] = fma2(bi, s_w2[i * 4 + p], acc2[p]);
    }
    float t2[8];
    #pragma unroll
    for (int p = 0; p < 4; p++) {
        float lo, hi;
        unpack2(acc2[p], lo, hi);
        t2[2 * p] = fmaxf(lo, 0.f);
        t2[2 * p + 1] = fmaxf(hi, 0.f);
    }

    // layer 3: 8 -> 4
    u64 acc3[2];
    acc3[0] = s_b3[0];
    acc3[1] = s_b3[1];
    #pragma unroll
    for (int i = 0; i < 8; i++) {
        u64 bi = pack2(t2[i]);
        acc3[0] = fma2(bi, s_w3[i * 2], acc3[0]);
        acc3[1] = fma2(bi, s_w3[i * 2 + 1], acc3[1]);
    }
    float e0, e1, e2, e3;
    unpack2(acc3[0], e0, e1);
    unpack2(acc3[1], e2, e3);

    // log_softmax(e) -> output region 2
    float mx = fmaxf(fmaxf(e0, e1), fmaxf(e2, e3));
    float x0 = __expf(e0 - mx), x1 = __expf(e1 - mx), x2 = __expf(e2 - mx), x3 = __expf(e3 - mx);
    float lse = mx + __logf(x0 + x1 + x2 + x3);
    reinterpret_cast<float4*>(out_e)[e] = make_float4(e0 - lse, e1 - lse, e2 - lse, e3 - lse);

    // layer-2 attention scatter: single vector red {ex*h20, ex*h21, ex, 0}
    float alpha = g_al2s[s] + g_al2d[d] + e0 * s_c2[0] + e1 * s_c2[1] + e2 * s_c2[2] + e3 * s_c2[3];
    float ex2 = __expf(leaky(alpha));
    float h20 = g_h2[s * 2], h21 = g_h2[s * 2 + 1];
    red_v4(g_acc2 + (size_t)d * 4, ex2 * h20, ex2 * h21, ex2, 0.f);

    // block-reduce sum of e for layer-2 self-loop mean
    float r0 = e0, r1 = e1, r2 = e2, r3 = e3;
    #pragma unroll
    for (int o = 16; o > 0; o >>= 1) {
        r0 += __shfl_down_sync(0xffffffffu, r0, o);
        r1 += __shfl_down_sync(0xffffffffu, r1, o);
        r2 += __shfl_down_sync(0xffffffffu, r2, o);
        r3 += __shfl_down_sync(0xffffffffu, r3, o);
    }
    int w = t >> 5;
    if ((t & 31) == 0) { sred[w * 4] = r0; sred[w * 4 + 1] = r1; sred[w * 4 + 2] = r2; sred[w * 4 + 3] = r3; }
    __syncthreads();
    if (t < 4) {
        float sAcc = 0.f;
        #pragma unroll
        for (int i = 0; i < 8; i++) sAcc += sred[i * 4 + t];
        atomicAdd(&g_esum[t], sAcc);
    }
}

// ---------------- K6: finalize layer 2 + node log_softmax ----------------
__global__ void __launch_bounds__(256) k_node3(const float* __restrict__ b2,
                                               float* __restrict__ out_n) {
    int n = blockIdx.x * 256 + threadIdx.x;
    if (n >= NN) return;
    const float invE = 1.f / (float)EE;
    float a = g_al2s[n] + g_al2d[n];
    #pragma unroll
    for (int j = 0; j < 4; j++) a += g_esum[j] * invE * g_c2[j];
    float ex = __expf(leaky(a));
    float4 acc = reinterpret_cast<const float4*>(g_acc2)[n];
    float den = 1.f / (acc.z + ex + 1e-16f);
    float h20 = g_h2[n * 2], h21 = g_h2[n * 2 + 1];
    float o0 = (acc.x + ex * h20) * den + b2[0];
    float o1 = (acc.y + ex * h21) * den + b2[1];
    float m = fmaxf(o0, o1);
    float l = m + __logf(__expf(o0 - m) + __expf(o1 - m));
    reinterpret_cast<float2*>(out_n)[n] = make_float2(o0 - l, o1 - l);
}

// ---------------- launch ----------------
extern "C" void kernel_launch(void* const* d_in, const int* in_sizes, int n_in,
                              void* d_out, int out_size) {
    const float* x   = (const float*)d_in[0];
    const float* ea  = (const float*)d_in[1];
    const float* W1  = (const float*)d_in[2];
    const float* as1 = (const float*)d_in[3];
    const float* ad1 = (const float*)d_in[4];
    const float* We1 = (const float*)d_in[5];
    const float* ae1 = (const float*)d_in[6];
    const float* b1  = (const float*)d_in[7];
    const float* mw0 = (const float*)d_in[8];
    const float* mb0 = (const float*)d_in[9];
    const float* mw1 = (const float*)d_in[10];
    const float* mb1 = (const float*)d_in[11];
    const float* mw2 = (const float*)d_in[12];
    const float* mb2 = (const float*)d_in[13];
    const float* mw3 = (const float*)d_in[14];
    const float* mb3 = (const float*)d_in[15];
    const float* W2  = (const float*)d_in[16];
    const float* as2 = (const float*)d_in[17];
    const float* ad2 = (const float*)d_in[18];
    const float* We2 = (const float*)d_in[19];
    const float* ae2 = (const float*)d_in[20];
    const float* b2  = (const float*)d_in[21];
    const int* ei    = (const int*)d_in[22];
    const int* srcp = ei;
    const int* dstp = ei + EE;
    float* out = (float*)d_out;

    k_prep<<<1, 32>>>(We1, ae1, We2, ae2);
    k_node1<<<(NN + 255) / 256, 256>>>(x, W1, as1, ad1);
    k_eamean<<<592, 256>>>(ea);
    k_edge1<<<EE / 256, 256>>>(srcp, dstp, ea, x);
    k_node2<<<(NN + 255) / 256, 256>>>(x, W1, b1, mw0, W2, as2, ad2);
    k_edge2<<<EE / 256, 256>>>(srcp, dstp, ea, mw0, mb0, mw1, mb1, mw2, mb2, mw3, mb3,
                               out + 2 * NN);
    k_node3<<<(NN + 255) / 256, 256>>>(b2, out);
}